// round 2
// baseline (speedup 1.0000x reference)
#include <cuda_runtime.h>
#include <math.h>

#define NN     50000
#define EE     600000
#define GG     256
#define HID    128
#define EDIM   16
#define EH     64
#define NL     4
#define MINF   200
#define MH     256
#define MOUT   128
#define PH     512
#define PIN    (HID + MOUT)

// ---------------- scratch (static device globals) -------------------------
__device__ float g_w[NL * EE];          // [l][e]
__device__ float g_deg[NN * NL];        // [n][l]  (v4-red friendly)
__device__ float g_dinv[NN * NL];       // [n][l]
__device__ float g_h[NN * HID];
__device__ float g_hl[NN * HID];        // hl' = dinv * (h @ lin_W)
__device__ float g_out[NN * HID];       // scatter accumulator (S)
__device__ float g_pool[GG * HID];
__device__ float g_cnt[GG];
__device__ float g_t0[GG * MH];
__device__ float g_t1[GG * MH];
__device__ float g_cat[GG * PIN];
__device__ float g_p0[GG * PH];
__device__ float g_p1[GG * PH];

// ---------------- v4 float reduction helper -------------------------------
__device__ __forceinline__ void red_add_v4(float* p, float a, float b, float c, float d)
{
    asm volatile("red.global.add.v4.f32 [%0], {%1, %2, %3, %4};"
                 :: "l"(p), "f"(a), "f"(b), "f"(c), "f"(d) : "memory");
}

// ---------------- edge MLP (all 4 layers fused) ---------------------------
__global__ __launch_bounds__(256) void edge_mlp_all(
    const float* __restrict__ ea, const float* __restrict__ mW1,
    const float* __restrict__ mb1, const float* __restrict__ mW2,
    const float* __restrict__ mb2)
{
    __shared__ float sW1t[NL][EH * EDIM];   // transposed: [l][j][k]
    __shared__ float sb1[NL][EH];
    __shared__ float sW2[NL][EH];
    __shared__ float sb2[NL];
    int t = threadIdx.x;
    for (int i = t; i < NL * EDIM * EH; i += 256) {
        int l = i / (EDIM * EH);
        int rem = i % (EDIM * EH);
        int k = rem / EH, j = rem % EH;
        sW1t[l][j * EDIM + k] = mW1[i];
    }
    for (int i = t; i < NL * EH; i += 256) {
        sb1[i / EH][i % EH] = mb1[i];
        sW2[i / EH][i % EH] = mW2[i];
    }
    if (t < NL) sb2[t] = mb2[t];
    __syncthreads();

    int e = blockIdx.x * 256 + t;
    if (e >= EE) return;
    float a[EDIM];
    const float4* eap = (const float4*)(ea + (size_t)e * EDIM);
#pragma unroll
    for (int q = 0; q < 4; q++) {
        float4 v = eap[q];
        a[q * 4 + 0] = v.x; a[q * 4 + 1] = v.y; a[q * 4 + 2] = v.z; a[q * 4 + 3] = v.w;
    }
#pragma unroll 1
    for (int l = 0; l < NL; l++) {
        float acc = sb2[l];
#pragma unroll 4
        for (int j = 0; j < EH; j++) {
            const float4* wp = (const float4*)&sW1t[l][j * EDIM];
            float s = sb1[l][j];
#pragma unroll
            for (int q = 0; q < 4; q++) {
                float4 w4 = wp[q];
                s = fmaf(a[q * 4 + 0], w4.x, s);
                s = fmaf(a[q * 4 + 1], w4.y, s);
                s = fmaf(a[q * 4 + 2], w4.z, s);
                s = fmaf(a[q * 4 + 3], w4.w, s);
            }
            acc = fmaf(fmaxf(s, 0.f), sW2[l][j], acc);
        }
        g_w[l * EE + e] = 1.f / (1.f + __expf(-acc));
    }
}

// ---------------- degree / norm -------------------------------------------
__global__ void deg_init()
{
    int i = blockIdx.x * blockDim.x + threadIdx.x;
    if (i < NL * NN) g_deg[i] = 1.0f;   // self loop weight
}

__global__ void deg_accum(const int* __restrict__ colp)
{
    int e = blockIdx.x * blockDim.x + threadIdx.x;
    if (e >= EE) return;
    int c = colp[e];
    float w0 = g_w[0 * EE + e];
    float w1 = g_w[1 * EE + e];
    float w2 = g_w[2 * EE + e];
    float w3 = g_w[3 * EE + e];
    red_add_v4(&g_deg[(size_t)c * NL], w0, w1, w2, w3);
}

__global__ void dinv_kernel()
{
    int i = blockIdx.x * blockDim.x + threadIdx.x;
    if (i < NL * NN) {
        float d = g_deg[i];
        g_dinv[i] = (d > 0.f) ? rsqrtf(d) : 0.f;
    }
}

// ---------------- node matmul: 64 rows x 128 cols per block ----------------
// out[row] = post( scale_out[row] * ( pre(in[row]) @ W ) + bias )
// pre(in[row][k])  = in_scale ? in[row][k]*in_scale[row*NL] + in_bias[k] : in[row][k]
__global__ __launch_bounds__(512) void node_mm(
    const float* __restrict__ in, const float* __restrict__ W,
    const float* __restrict__ in_scale, const float* __restrict__ in_bias,
    const float* __restrict__ bias, float* __restrict__ out,
    const float* __restrict__ out_scale, int do_relu)
{
    __shared__ float sin_t[128 * 68];   // [k][row], stride 68 (mult of 4)
    const int t = threadIdx.x;
    const int base = blockIdx.x * 64;

#pragma unroll
    for (int it = 0; it < 4; it++) {
        int idx4 = t + it * 512;           // 2048 float4 tiles
        int row = idx4 >> 5;               // 0..63
        int k4  = idx4 & 31;               // 0..31
        int grow = base + row;
        float4 v = make_float4(0.f, 0.f, 0.f, 0.f);
        if (grow < NN) {
            v = *(const float4*)&in[(size_t)grow * HID + k4 * 4];
            if (in_scale) {
                float s = in_scale[(size_t)grow * NL];
                v.x = fmaf(v.x, s, in_bias[k4 * 4 + 0]);
                v.y = fmaf(v.y, s, in_bias[k4 * 4 + 1]);
                v.z = fmaf(v.z, s, in_bias[k4 * 4 + 2]);
                v.w = fmaf(v.w, s, in_bias[k4 * 4 + 3]);
            }
        }
        sin_t[(k4 * 4 + 0) * 68 + row] = v.x;
        sin_t[(k4 * 4 + 1) * 68 + row] = v.y;
        sin_t[(k4 * 4 + 2) * 68 + row] = v.z;
        sin_t[(k4 * 4 + 3) * 68 + row] = v.w;
    }
    __syncthreads();

    const int cx = t & 31;   // cols 4*cx..+3
    const int ry = t >> 5;   // rows 4*ry..+3  (warp-uniform -> LDS broadcast)
    float acc[4][4];
    float4 bv = bias ? *(const float4*)&bias[cx * 4] : make_float4(0.f, 0.f, 0.f, 0.f);
#pragma unroll
    for (int r = 0; r < 4; r++) {
        acc[r][0] = bv.x; acc[r][1] = bv.y; acc[r][2] = bv.z; acc[r][3] = bv.w;
    }
#pragma unroll 8
    for (int k = 0; k < 128; k++) {
        float4 wv = *(const float4*)&W[(size_t)k * HID + cx * 4];
        float4 iv = *(const float4*)&sin_t[k * 68 + ry * 4];
        acc[0][0] = fmaf(iv.x, wv.x, acc[0][0]); acc[0][1] = fmaf(iv.x, wv.y, acc[0][1]);
        acc[0][2] = fmaf(iv.x, wv.z, acc[0][2]); acc[0][3] = fmaf(iv.x, wv.w, acc[0][3]);
        acc[1][0] = fmaf(iv.y, wv.x, acc[1][0]); acc[1][1] = fmaf(iv.y, wv.y, acc[1][1]);
        acc[1][2] = fmaf(iv.y, wv.z, acc[1][2]); acc[1][3] = fmaf(iv.y, wv.w, acc[1][3]);
        acc[2][0] = fmaf(iv.z, wv.x, acc[2][0]); acc[2][1] = fmaf(iv.z, wv.y, acc[2][1]);
        acc[2][2] = fmaf(iv.z, wv.z, acc[2][2]); acc[2][3] = fmaf(iv.z, wv.w, acc[2][3]);
        acc[3][0] = fmaf(iv.w, wv.x, acc[3][0]); acc[3][1] = fmaf(iv.w, wv.y, acc[3][1]);
        acc[3][2] = fmaf(iv.w, wv.z, acc[3][2]); acc[3][3] = fmaf(iv.w, wv.w, acc[3][3]);
    }
#pragma unroll
    for (int r = 0; r < 4; r++) {
        int grow = base + ry * 4 + r;
        if (grow < NN) {
            float os = out_scale ? out_scale[(size_t)grow * NL] : 1.f;
            float4 o = make_float4(acc[r][0] * os, acc[r][1] * os,
                                   acc[r][2] * os, acc[r][3] * os);
            if (do_relu) {
                o.x = fmaxf(o.x, 0.f); o.y = fmaxf(o.y, 0.f);
                o.z = fmaxf(o.z, 0.f); o.w = fmaxf(o.w, 0.f);
            }
            *(float4*)&out[(size_t)grow * HID + cx * 4] = o;
        }
    }
}

// ---------------- edge scatter: 32 lanes x v4-red per edge -----------------
__global__ __launch_bounds__(256) void scatter(
    const int* __restrict__ rowp, const int* __restrict__ colp,
    const float* __restrict__ w)
{
    int gid = blockIdx.x * 256 + threadIdx.x;
    int e = gid >> 5;
    int lane = gid & 31;
    if (e >= EE) return;
    int r = rowp[e], c = colp[e];
    float nrm = w[e];
    float4 v = ((const float4*)(g_hl + (size_t)r * HID))[lane];
    red_add_v4(g_out + (size_t)c * HID + lane * 4,
               nrm * v.x, nrm * v.y, nrm * v.z, nrm * v.w);
}

// ---------------- mean pool -----------------------------------------------
__global__ void pool_init()
{
    int i = blockIdx.x * blockDim.x + threadIdx.x;
    if (i < GG * HID) g_pool[i] = 0.f;
    if (i < GG) g_cnt[i] = 0.f;
}

__global__ void pool_cnt(const int* __restrict__ batch)
{
    int i = blockIdx.x * blockDim.x + threadIdx.x;
    if (i < NN) atomicAdd(&g_cnt[batch[i]], 1.f);
}

__global__ void pool_accum(const int* __restrict__ batch)
{
    int idx = blockIdx.x * blockDim.x + threadIdx.x;   // NN*32 v4 tiles
    if (idx >= NN * 32) return;
    int i = idx >> 5, j4 = idx & 31;
    float4 v = ((const float4*)(g_h + (size_t)i * HID))[j4];
    red_add_v4(&g_pool[(size_t)batch[i] * HID + j4 * 4], v.x, v.y, v.z, v.w);
}

__global__ void pool_final()
{
    int idx = blockIdx.x * blockDim.x + threadIdx.x;
    if (idx < GG * HID) g_pool[idx] /= fmaxf(g_cnt[idx >> 7], 1.f);
}

// ---------------- small dense layers --------------------------------------
__global__ __launch_bounds__(256) void dense(
    const float* __restrict__ in, const float* __restrict__ W,
    const float* __restrict__ b, float* __restrict__ out,
    int K, int Nout, int do_relu)
{
    __shared__ float sin[512];
    int row = blockIdx.x;
    for (int i = threadIdx.x; i < K; i += blockDim.x) sin[i] = in[(size_t)row * K + i];
    __syncthreads();
    for (int j = threadIdx.x; j < Nout; j += blockDim.x) {
        float acc = b[j];
        for (int k = 0; k < K; k++) acc = fmaf(sin[k], W[(size_t)k * Nout + j], acc);
        out[(size_t)row * Nout + j] = do_relu ? fmaxf(acc, 0.f) : acc;
    }
}

__global__ void concat_kernel()
{
    int idx = blockIdx.x * blockDim.x + threadIdx.x;
    if (idx >= GG * PIN) return;
    int g = idx / PIN, j = idx % PIN;
    g_cat[idx] = (j < HID) ? g_pool[g * HID + j] : g_t1[g * MOUT + (j - HID)];
}

__global__ __launch_bounds__(128) void final_out(
    const float* __restrict__ W, const float* __restrict__ b,
    float* __restrict__ out)
{
    int g = blockIdx.x, t = threadIdx.x;
    float acc = 0.f;
    for (int k = t; k < PH; k += 128) acc = fmaf(g_p1[(size_t)g * PH + k], W[k], acc);
#pragma unroll
    for (int off = 16; off; off >>= 1) acc += __shfl_xor_sync(0xFFFFFFFFu, acc, off);
    __shared__ float s[4];
    if ((t & 31) == 0) s[t >> 5] = acc;
    __syncthreads();
    if (t == 0) out[g] = s[0] + s[1] + s[2] + s[3] + b[0];
}

// ---------------- launch --------------------------------------------------
extern "C" void kernel_launch(void* const* d_in, const int* in_sizes, int n_in,
                              void* d_out, int out_size)
{
    const float* x     = (const float*)d_in[0];
    const int*   ei    = (const int*)d_in[1];
    const float* ea    = (const float*)d_in[2];
    const int*   batch = (const int*)d_in[3];
    const float* mol   = (const float*)d_in[4];
    const float* clinW = (const float*)d_in[5];
    const float* cmW1  = (const float*)d_in[6];
    const float* cmb1  = (const float*)d_in[7];
    const float* cmW2  = (const float*)d_in[8];
    const float* cmb2  = (const float*)d_in[9];
    const float* cbias = (const float*)d_in[10];
    const float* gcnW  = (const float*)d_in[11];
    const float* gcnb  = (const float*)d_in[12];
    const float* mW0 = (const float*)d_in[13]; const float* mb0 = (const float*)d_in[14];
    const float* mW1 = (const float*)d_in[15]; const float* mb1 = (const float*)d_in[16];
    const float* mW2 = (const float*)d_in[17]; const float* mb2 = (const float*)d_in[18];
    const float* mW3 = (const float*)d_in[19]; const float* mb3 = (const float*)d_in[20];
    const float* pW0 = (const float*)d_in[21]; const float* pb0 = (const float*)d_in[22];
    const float* pW1 = (const float*)d_in[23]; const float* pb1 = (const float*)d_in[24];
    const float* oW  = (const float*)d_in[25]; const float* ob  = (const float*)d_in[26];
    float* out = (float*)d_out;

    const int* rowp = ei;
    const int* colp = ei + EE;

    static float *h_ptr = nullptr, *hl_ptr = nullptr, *out_ptr = nullptr;
    static float *w_ptr = nullptr, *dinv_ptr = nullptr;
    static float *t0_p = nullptr, *t1_p = nullptr;
    static float *cat_p = nullptr, *p0_p = nullptr, *p1_p = nullptr;
    if (!h_ptr) {
        cudaGetSymbolAddress((void**)&h_ptr, g_h);
        cudaGetSymbolAddress((void**)&hl_ptr, g_hl);
        cudaGetSymbolAddress((void**)&out_ptr, g_out);
        cudaGetSymbolAddress((void**)&w_ptr, g_w);
        cudaGetSymbolAddress((void**)&dinv_ptr, g_dinv);
        cudaGetSymbolAddress((void**)&t0_p, g_t0);
        cudaGetSymbolAddress((void**)&t1_p, g_t1);
        cudaGetSymbolAddress((void**)&cat_p, g_cat);
        cudaGetSymbolAddress((void**)&p0_p, g_p0);
        cudaGetSymbolAddress((void**)&p1_p, g_p1);
    }

    // edge gates + degree norms for all layers up-front
    edge_mlp_all<<<(EE + 255) / 256, 256>>>(ea, cmW1, cmb1, cmW2, cmb2);
    deg_init<<<(NL * NN + 255) / 256, 256>>>();
    deg_accum<<<(EE + 255) / 256, 256>>>(colp);
    dinv_kernel<<<(NL * NN + 255) / 256, 256>>>();

    const int mm_grid = (NN + 63) / 64;
    for (int l = 0; l < NL; l++) {
        const float* hin = (l == 0) ? x : h_ptr;
        // hl' = dinv * (h @ lin_W)
        node_mm<<<mm_grid, 512>>>(hin, clinW + (size_t)l * HID * HID,
                                  nullptr, nullptr, nullptr,
                                  hl_ptr, dinv_ptr + l, 0);
        // S init with self-loop term (== hl'), then scatter w[e] * hl'[row]
        cudaMemcpyAsync(out_ptr, hl_ptr, (size_t)NN * HID * sizeof(float),
                        cudaMemcpyDeviceToDevice);
        scatter<<<(EE * 32 + 255) / 256, 256>>>(rowp, colp, w_ptr + (size_t)l * EE);
        // h = relu( (dinv*S + conv_bias) @ gcn_W + gcn_b )
        node_mm<<<mm_grid, 512>>>(out_ptr, gcnW + (size_t)l * HID * HID,
                                  dinv_ptr + l, cbias + (size_t)l * HID,
                                  gcnb + (size_t)l * HID, h_ptr, nullptr, 1);
    }

    pool_init<<<(GG * HID + 255) / 256, 256>>>();
    pool_cnt<<<(NN + 255) / 256, 256>>>(batch);
    pool_accum<<<(NN * 32 + 255) / 256, 256>>>(batch);
    pool_final<<<(GG * HID + 255) / 256, 256>>>();

    dense<<<GG, 256>>>(mol,  mW0, mb0, t0_p, MINF, MH,   1);
    dense<<<GG, 256>>>(t0_p, mW1, mb1, t1_p, MH,   MH,   1);
    dense<<<GG, 256>>>(t1_p, mW2, mb2, t0_p, MH,   MH,   1);
    dense<<<GG, 256>>>(t0_p, mW3, mb3, t1_p, MH,   MOUT, 1);

    concat_kernel<<<(GG * PIN + 255) / 256, 256>>>();

    dense<<<GG, 256>>>(cat_p, pW0, pb0, p0_p, PIN, PH, 1);
    dense<<<GG, 256>>>(p0_p,  pW1, pb1, p1_p, PH,  PH, 1);
    final_out<<<GG, 128>>>(oW, ob, out);
}

// round 3
// speedup vs baseline: 1.5764x; 1.5764x over previous
#include <cuda_runtime.h>
#include <math.h>

#define NN     50000
#define EE     600000
#define GG     256
#define HID    128
#define EDIM   16
#define EH     64
#define NL     4
#define MINF   200
#define MH     256
#define MOUT   128
#define PH     512
#define PIN    (HID + MOUT)

typedef unsigned long long ull;

// ---------------- scratch (static device globals) -------------------------
__device__ float g_w[NL * EE];          // [l][e] edge gates
__device__ float g_dinv[NN * NL];       // [n][l]
__device__ float g_h[NN * HID];
__device__ float g_hl[NN * HID];        // hl' = dinv * (h @ lin_W)
__device__ float g_out[NN * HID];       // aggregated S'
__device__ int   g_cnt_csr[NN];
__device__ int   g_ptr[NN + 1];
__device__ int   g_cursor[NN];
__device__ int2  g_se[EE];              // (src, eid) grouped by dst
__device__ float g_pool[GG * HID];
__device__ float g_cnt[GG];
__device__ float g_t0[GG * MH];
__device__ float g_t1[GG * MH];
__device__ float g_cat[GG * PIN];
__device__ float g_p0[GG * PH];
__device__ float g_p1[GG * PH];

// ---------------- f32x2 helpers -------------------------------------------
__device__ __forceinline__ ull pack2(float a, float b)
{
    ull r; asm("mov.b64 %0, {%1, %2};" : "=l"(r) : "f"(a), "f"(b)); return r;
}
__device__ __forceinline__ void unpack2(ull p, float& a, float& b)
{
    asm("mov.b64 {%0, %1}, %2;" : "=f"(a), "=f"(b) : "l"(p));
}
#define FMA2(d, a, b, c) \
    asm("fma.rn.f32x2 %0, %1, %2, %3;" : "=l"(d) : "l"(a), "l"(b), "l"(c))

// ---------------- CSR build -----------------------------------------------
__global__ void zero_cnt()
{
    int i = blockIdx.x * blockDim.x + threadIdx.x;
    if (i < NN) g_cnt_csr[i] = 0;
}

__global__ void hist(const int* __restrict__ colp)
{
    int e = blockIdx.x * blockDim.x + threadIdx.x;
    if (e < EE) atomicAdd(&g_cnt_csr[colp[e]], 1);
}

__global__ __launch_bounds__(1024) void scan_kernel()
{
    __shared__ int s[1024];
    int t = threadIdx.x;
    int carry = 0;
    for (int base = 0; base < NN; base += 1024) {
        int i = base + t;
        int v = (i < NN) ? g_cnt_csr[i] : 0;
        s[t] = v;
        __syncthreads();
#pragma unroll
        for (int off = 1; off < 1024; off <<= 1) {
            int add = (t >= off) ? s[t - off] : 0;
            __syncthreads();
            s[t] += add;
            __syncthreads();
        }
        int excl = s[t] - v;
        if (i < NN) {
            g_ptr[i] = carry + excl;
            g_cursor[i] = carry + excl;
        }
        int tot = s[1023];
        __syncthreads();
        carry += tot;
    }
    if (t == 0) g_ptr[NN] = carry;
}

__global__ void fill_csr(const int* __restrict__ rowp, const int* __restrict__ colp)
{
    int e = blockIdx.x * blockDim.x + threadIdx.x;
    if (e >= EE) return;
    int c = colp[e];
    int pos = atomicAdd(&g_cursor[c], 1);
    g_se[pos] = make_int2(rowp[e], e);
}

// ---------------- edge MLP: 2 edges/thread, f32x2 packed ------------------
__global__ __launch_bounds__(256) void edge_mlp_all(
    const float* __restrict__ ea, const float* __restrict__ mW1,
    const float* __restrict__ mb1, const float* __restrict__ mW2,
    const float* __restrict__ mb2)
{
    __shared__ ull   sW1p[NL][EH * EDIM];   // dup-packed (w,w), [l][j][k]
    __shared__ ull   sb1p[NL][EH];
    __shared__ float sW2[NL][EH];
    __shared__ float sb2[NL];
    int t = threadIdx.x;
    for (int i = t; i < NL * EDIM * EH; i += 256) {
        int l = i / (EDIM * EH);
        int rem = i % (EDIM * EH);
        int k = rem / EH, j = rem % EH;      // mW1 is [l][k][j]
        float w = mW1[i];
        sW1p[l][j * EDIM + k] = pack2(w, w);
    }
    for (int i = t; i < NL * EH; i += 256) {
        float b = mb1[i];
        sb1p[i / EH][i % EH] = pack2(b, b);
        sW2[i / EH][i % EH] = mW2[i];
    }
    if (t < NL) sb2[t] = mb2[t];
    __syncthreads();

    int gid = blockIdx.x * 256 + t;          // pair index
    if (gid >= EE / 2) return;
    int e0 = gid * 2;

    ull ap[EDIM];
    {
        const float4* p0 = (const float4*)(ea + (size_t)e0 * EDIM);
        const float4* p1 = (const float4*)(ea + (size_t)(e0 + 1) * EDIM);
#pragma unroll
        for (int q = 0; q < 4; q++) {
            float4 a0 = p0[q], a1 = p1[q];
            ap[q * 4 + 0] = pack2(a0.x, a1.x);
            ap[q * 4 + 1] = pack2(a0.y, a1.y);
            ap[q * 4 + 2] = pack2(a0.z, a1.z);
            ap[q * 4 + 3] = pack2(a0.w, a1.w);
        }
    }

#pragma unroll 1
    for (int l = 0; l < NL; l++) {
        float acc0 = sb2[l], acc1 = acc0;
#pragma unroll 2
        for (int j = 0; j < EH; j++) {
            const ull* wp = &sW1p[l][j * EDIM];
            ull sa = sb1p[l][j];
            ull sb = pack2(0.f, 0.f);
#pragma unroll
            for (int k = 0; k < EDIM; k += 2) {
                FMA2(sa, ap[k + 0], wp[k + 0], sa);
                FMA2(sb, ap[k + 1], wp[k + 1], sb);
            }
            float s0a, s1a, s0b, s1b;
            unpack2(sa, s0a, s1a);
            unpack2(sb, s0b, s1b);
            float w2 = sW2[l][j];
            acc0 = fmaf(fmaxf(s0a + s0b, 0.f), w2, acc0);
            acc1 = fmaf(fmaxf(s1a + s1b, 0.f), w2, acc1);
        }
        float2 o;
        o.x = 1.f / (1.f + __expf(-acc0));
        o.y = 1.f / (1.f + __expf(-acc1));
        ((float2*)(g_w + (size_t)l * EE))[gid] = o;
    }
}

// ---------------- degree + dinv via CSR (all layers) ----------------------
__global__ void deg_dinv()
{
    int n = blockIdx.x * blockDim.x + threadIdx.x;
    if (n >= NN) return;
    int beg = g_ptr[n], end = g_ptr[n + 1];
    float d0 = 1.f, d1 = 1.f, d2 = 1.f, d3 = 1.f;
    for (int i = beg; i < end; i++) {
        int eid = g_se[i].y;
        d0 += g_w[0 * EE + eid];
        d1 += g_w[1 * EE + eid];
        d2 += g_w[2 * EE + eid];
        d3 += g_w[3 * EE + eid];
    }
    g_dinv[n * NL + 0] = rsqrtf(d0);
    g_dinv[n * NL + 1] = rsqrtf(d1);
    g_dinv[n * NL + 2] = rsqrtf(d2);
    g_dinv[n * NL + 3] = rsqrtf(d3);
}

// ---------------- gather-aggregate: 1 warp per node -----------------------
__global__ __launch_bounds__(256) void agg(const float* __restrict__ w)
{
    int gid = blockIdx.x * 256 + threadIdx.x;
    int n = gid >> 5;
    if (n >= NN) return;
    int lane = gid & 31;
    const float4* hlv = (const float4*)g_hl;
    float4 acc = hlv[(size_t)n * 32 + lane];      // self-loop term = hl'[n]
    int beg = g_ptr[n], end = g_ptr[n + 1];

    if (beg < end) {
        int2 se = __ldg(&g_se[beg]);
        float wt = __ldg(&w[se.y]);
        for (int i = beg; i < end; i++) {
            int2 se_n; float wt_n;
            if (i + 1 < end) {
                se_n = __ldg(&g_se[i + 1]);
                wt_n = __ldg(&w[se_n.y]);
            }
            float4 v = hlv[(size_t)se.x * 32 + lane];
            acc.x = fmaf(wt, v.x, acc.x);
            acc.y = fmaf(wt, v.y, acc.y);
            acc.z = fmaf(wt, v.z, acc.z);
            acc.w = fmaf(wt, v.w, acc.w);
            se = se_n; wt = wt_n;
        }
    }
    ((float4*)g_out)[(size_t)n * 32 + lane] = acc;
}

// ---------------- node matmul: 16 rows x 128 cols per block ---------------
// out = post( out_scale[row] * ( (in[row]*in_scale[row] + in_bias) @ W ) + bias )
__global__ __launch_bounds__(128) void node_mm(
    const float* __restrict__ in, const float* __restrict__ W,
    const float* __restrict__ in_scale, const float* __restrict__ in_bias,
    const float* __restrict__ bias, float* __restrict__ out,
    const float* __restrict__ out_scale, int do_relu)
{
    __shared__ float sin_t[128 * 20];   // [k][row], padded
    const int t = threadIdx.x;
    const int base = blockIdx.x * 16;
    for (int idx = t; idx < 16 * 128; idx += 128) {
        int row = idx >> 7, k = idx & 127;
        int grow = base + row;
        float v = 0.f;
        if (grow < NN) {
            v = in[(size_t)grow * HID + k];
            if (in_scale) v = fmaf(v, in_scale[(size_t)grow * NL], in_bias[k]);
        }
        sin_t[k * 20 + row] = v;
    }
    __syncthreads();

    const int cx = t & 31;
    const int ry = t >> 5;
    float acc[4][4];
    float4 bv = bias ? *(const float4*)&bias[cx * 4] : make_float4(0.f, 0.f, 0.f, 0.f);
#pragma unroll
    for (int r = 0; r < 4; r++) {
        acc[r][0] = bv.x; acc[r][1] = bv.y; acc[r][2] = bv.z; acc[r][3] = bv.w;
    }
#pragma unroll 8
    for (int k = 0; k < 128; k++) {
        float4 wv = *(const float4*)&W[(size_t)k * HID + cx * 4];
        float4 iv = *(const float4*)&sin_t[k * 20 + ry * 4];
        acc[0][0] = fmaf(iv.x, wv.x, acc[0][0]); acc[0][1] = fmaf(iv.x, wv.y, acc[0][1]);
        acc[0][2] = fmaf(iv.x, wv.z, acc[0][2]); acc[0][3] = fmaf(iv.x, wv.w, acc[0][3]);
        acc[1][0] = fmaf(iv.y, wv.x, acc[1][0]); acc[1][1] = fmaf(iv.y, wv.y, acc[1][1]);
        acc[1][2] = fmaf(iv.y, wv.z, acc[1][2]); acc[1][3] = fmaf(iv.y, wv.w, acc[1][3]);
        acc[2][0] = fmaf(iv.z, wv.x, acc[2][0]); acc[2][1] = fmaf(iv.z, wv.y, acc[2][1]);
        acc[2][2] = fmaf(iv.z, wv.z, acc[2][2]); acc[2][3] = fmaf(iv.z, wv.w, acc[2][3]);
        acc[3][0] = fmaf(iv.w, wv.x, acc[3][0]); acc[3][1] = fmaf(iv.w, wv.y, acc[3][1]);
        acc[3][2] = fmaf(iv.w, wv.z, acc[3][2]); acc[3][3] = fmaf(iv.w, wv.w, acc[3][3]);
    }
#pragma unroll
    for (int r = 0; r < 4; r++) {
        int grow = base + ry * 4 + r;
        if (grow < NN) {
            float os = out_scale ? out_scale[(size_t)grow * NL] : 1.f;
            float4 o = make_float4(acc[r][0] * os, acc[r][1] * os,
                                   acc[r][2] * os, acc[r][3] * os);
            if (do_relu) {
                o.x = fmaxf(o.x, 0.f); o.y = fmaxf(o.y, 0.f);
                o.z = fmaxf(o.z, 0.f); o.w = fmaxf(o.w, 0.f);
            }
            *(float4*)&out[(size_t)grow * HID + cx * 4] = o;
        }
    }
}

// ---------------- mean pool -----------------------------------------------
__global__ void pool_init()
{
    int i = blockIdx.x * blockDim.x + threadIdx.x;
    if (i < GG * HID) g_pool[i] = 0.f;
    if (i < GG) g_cnt[i] = 0.f;
}

__global__ void pool_cnt(const int* __restrict__ batch)
{
    int i = blockIdx.x * blockDim.x + threadIdx.x;
    if (i < NN) atomicAdd(&g_cnt[batch[i]], 1.f);
}

__global__ void pool_accum(const int* __restrict__ batch)
{
    int idx = blockIdx.x * blockDim.x + threadIdx.x;
    if (idx >= NN * HID) return;
    int i = idx >> 7, j = idx & 127;
    atomicAdd(&g_pool[batch[i] * HID + j], g_h[idx]);
}

__global__ void pool_final()
{
    int idx = blockIdx.x * blockDim.x + threadIdx.x;
    if (idx < GG * HID) g_pool[idx] /= fmaxf(g_cnt[idx >> 7], 1.f);
}

// ---------------- small dense layers --------------------------------------
__global__ __launch_bounds__(256) void dense(
    const float* __restrict__ in, const float* __restrict__ W,
    const float* __restrict__ b, float* __restrict__ out,
    int K, int Nout, int do_relu)
{
    __shared__ float sin[512];
    int row = blockIdx.x;
    for (int i = threadIdx.x; i < K; i += blockDim.x) sin[i] = in[(size_t)row * K + i];
    __syncthreads();
    for (int j = threadIdx.x; j < Nout; j += blockDim.x) {
        float acc = b[j];
        for (int k = 0; k < K; k++) acc = fmaf(sin[k], W[(size_t)k * Nout + j], acc);
        out[(size_t)row * Nout + j] = do_relu ? fmaxf(acc, 0.f) : acc;
    }
}

__global__ void concat_kernel()
{
    int idx = blockIdx.x * blockDim.x + threadIdx.x;
    if (idx >= GG * PIN) return;
    int g = idx / PIN, j = idx % PIN;
    g_cat[idx] = (j < HID) ? g_pool[g * HID + j] : g_t1[g * MOUT + (j - HID)];
}

__global__ __launch_bounds__(128) void final_out(
    const float* __restrict__ W, const float* __restrict__ b,
    float* __restrict__ out)
{
    int g = blockIdx.x, t = threadIdx.x;
    float acc = 0.f;
    for (int k = t; k < PH; k += 128) acc = fmaf(g_p1[(size_t)g * PH + k], W[k], acc);
#pragma unroll
    for (int off = 16; off; off >>= 1) acc += __shfl_xor_sync(0xFFFFFFFFu, acc, off);
    __shared__ float s[4];
    if ((t & 31) == 0) s[t >> 5] = acc;
    __syncthreads();
    if (t == 0) out[g] = s[0] + s[1] + s[2] + s[3] + b[0];
}

// ---------------- launch --------------------------------------------------
extern "C" void kernel_launch(void* const* d_in, const int* in_sizes, int n_in,
                              void* d_out, int out_size)
{
    const float* x     = (const float*)d_in[0];
    const int*   ei    = (const int*)d_in[1];
    const float* ea    = (const float*)d_in[2];
    const int*   batch = (const int*)d_in[3];
    const float* mol   = (const float*)d_in[4];
    const float* clinW = (const float*)d_in[5];
    const float* cmW1  = (const float*)d_in[6];
    const float* cmb1  = (const float*)d_in[7];
    const float* cmW2  = (const float*)d_in[8];
    const float* cmb2  = (const float*)d_in[9];
    const float* cbias = (const float*)d_in[10];
    const float* gcnW  = (const float*)d_in[11];
    const float* gcnb  = (const float*)d_in[12];
    const float* mW0 = (const float*)d_in[13]; const float* mb0 = (const float*)d_in[14];
    const float* mW1 = (const float*)d_in[15]; const float* mb1 = (const float*)d_in[16];
    const float* mW2 = (const float*)d_in[17]; const float* mb2 = (const float*)d_in[18];
    const float* mW3 = (const float*)d_in[19]; const float* mb3 = (const float*)d_in[20];
    const float* pW0 = (const float*)d_in[21]; const float* pb0 = (const float*)d_in[22];
    const float* pW1 = (const float*)d_in[23]; const float* pb1 = (const float*)d_in[24];
    const float* oW  = (const float*)d_in[25]; const float* ob  = (const float*)d_in[26];
    float* out = (float*)d_out;

    const int* rowp = ei;
    const int* colp = ei + EE;

    static float *h_ptr = nullptr, *hl_ptr = nullptr, *out_ptr = nullptr;
    static float *w_ptr = nullptr, *dinv_ptr = nullptr;
    static float *t0_p = nullptr, *t1_p = nullptr;
    static float *cat_p = nullptr, *p0_p = nullptr, *p1_p = nullptr;
    if (!h_ptr) {
        cudaGetSymbolAddress((void**)&h_ptr, g_h);
        cudaGetSymbolAddress((void**)&hl_ptr, g_hl);
        cudaGetSymbolAddress((void**)&out_ptr, g_out);
        cudaGetSymbolAddress((void**)&w_ptr, g_w);
        cudaGetSymbolAddress((void**)&dinv_ptr, g_dinv);
        cudaGetSymbolAddress((void**)&t0_p, g_t0);
        cudaGetSymbolAddress((void**)&t1_p, g_t1);
        cudaGetSymbolAddress((void**)&cat_p, g_cat);
        cudaGetSymbolAddress((void**)&p0_p, g_p0);
        cudaGetSymbolAddress((void**)&p1_p, g_p1);
    }

    // CSR by destination (per call; edge order inside a node is atomic-raced,
    // only affects fp32 summation order, within tolerance like the atomics were)
    zero_cnt<<<(NN + 255) / 256, 256>>>();
    hist<<<(EE + 255) / 256, 256>>>(colp);
    scan_kernel<<<1, 1024>>>();
    fill_csr<<<(EE + 255) / 256, 256>>>(rowp, colp);

    // edge gates (all layers) + degree norms
    edge_mlp_all<<<(EE / 2 + 255) / 256, 256>>>(ea, cmW1, cmb1, cmW2, cmb2);
    deg_dinv<<<(NN + 255) / 256, 256>>>();

    const int mm_grid = (NN + 15) / 16;
    for (int l = 0; l < NL; l++) {
        const float* hin = (l == 0) ? x : h_ptr;
        // hl' = dinv * (h @ lin_W)
        node_mm<<<mm_grid, 128>>>(hin, clinW + (size_t)l * HID * HID,
                                  nullptr, nullptr, nullptr,
                                  hl_ptr, dinv_ptr + l, 0);
        // S'[c] = hl'[c] + sum w[e] * hl'[src]   (gather, no atomics)
        agg<<<(NN * 32 + 255) / 256, 256>>>(w_ptr + (size_t)l * EE);
        // h = relu( (dinv*S' + conv_bias) @ gcn_W + gcn_b )
        node_mm<<<mm_grid, 128>>>(out_ptr, gcnW + (size_t)l * HID * HID,
                                  dinv_ptr + l, cbias + (size_t)l * HID,
                                  gcnb + (size_t)l * HID, h_ptr, nullptr, 1);
    }

    pool_init<<<(GG * HID + 255) / 256, 256>>>();
    pool_cnt<<<(NN + 255) / 256, 256>>>(batch);
    pool_accum<<<(NN * HID + 255) / 256, 256>>>(batch);
    pool_final<<<(GG * HID + 255) / 256, 256>>>();

    dense<<<GG, 256>>>(mol,  mW0, mb0, t0_p, MINF, MH,   1);
    dense<<<GG, 256>>>(t0_p, mW1, mb1, t1_p, MH,   MH,   1);
    dense<<<GG, 256>>>(t1_p, mW2, mb2, t0_p, MH,   MH,   1);
    dense<<<GG, 256>>>(t0_p, mW3, mb3, t1_p, MH,   MOUT, 1);

    concat_kernel<<<(GG * PIN + 255) / 256, 256>>>();

    dense<<<GG, 256>>>(cat_p, pW0, pb0, p0_p, PIN, PH, 1);
    dense<<<GG, 256>>>(p0_p,  pW1, pb1, p1_p, PH,  PH, 1);
    final_out<<<GG, 128>>>(oW, ob, out);
}